// round 5
// baseline (speedup 1.0000x reference)
#include <cuda_runtime.h>

// ---------------- problem constants ----------------
#define D_HIST   64
#define N_PIX    65536           // 256*256
#define LOf      (-3.0f)
#define Hstep    (6.0f / 63.0f)  // linspace(-3,3,64) spacing
#define A2       (4.0e-4f)       // FALL_OFF^2 = 0.02^2
#define EPSf     (1e-6f)

// ---------------- kernel tiling --------------------
#define NCOMBO   48              // 2 imgs * 8 batch * 3 channels
#define NCHUNK   32              // pixel chunks per combo
#define CHUNK    2048            // pixels per chunk
#define PIX      32              // pixels per inner iteration
#define ITERS    (CHUNK / PIX)
#define THREADS  256

// ---------------- scratch (static device memory, no allocs) ----------------
__device__ __align__(16) unsigned long long g_partial[NCOMBO * NCHUNK][2048]; // 25.2 MB (4096 f32 as 2048 u64 per block)
__device__ float g_hist[NCOMBO][4096];
__device__ float g_csum[NCOMBO];
__device__ float g_hb[8];

// fast reciprocal: bit trick + 2 Newton iterations (no MUFU)
__device__ __forceinline__ float frcp_nt(float q) {
    float r = __uint_as_float(0x7EF311C3u - __float_as_uint(q));
    r = r * fmaf(-q, r, 2.0f);
    r = r * fmaf(-q, r, 2.0f);
    return r;
}

// packed fp32x2 FMA (Blackwell FFMA2)
#define FMA2(d, a, b, c) \
    asm("fma.rn.f32x2 %0, %1, %2, %3;" : "=l"(d) : "l"(a), "l"(b), "l"(c))

// =====================================================================
// K1: per-(img,b,ch,chunk) partial 64x64 histogram
// =====================================================================
__global__ void __launch_bounds__(THREADS) hist_kernel(const float* __restrict__ x,
                                                       const float* __restrict__ y) {
    const int bx    = blockIdx.x;
    const int co    = bx >> 5;       // combo: img*24 + b*3 + ch
    const int chunk = bx & 31;
    const int img = co / 24;
    const int rem = co % 24;
    const int b   = rem / 3;
    const int ch  = rem % 3;
    const float* base = (img ? y : x) + (size_t)b * 3 * N_PIX;

    // u = l[ch]-l[cu], v = l[ch]-l[cv]
    const int up_tab[3] = {1, 0, 0};
    const int vp_tab[3] = {2, 2, 1};
    const int cu = up_tab[ch];
    const int cv = vp_tab[ch];

    __shared__ float su[PIX], sv[PIX], siy[PIX];
    __shared__ __align__(16) unsigned long long swu[PIX][64]; // (w,w) pairs, one per u-bin
    __shared__ __align__(16) unsigned long long swv[PIX][32]; // packed (w_{2k}, w_{2k+1})

    const int t  = threadIdx.x;
    const int ug = t >> 3;  // 0..31 -> u rows {2ug, 2ug+1}
    const int vg = t & 7;   // 0..7  -> v cols {8vg .. 8vg+7}

    // weight-gen: this thread owns bin (isU, k) for 16 pixels (uniform per warp)
    const int  kk    = t & 127;
    const bool isU   = (kk < 64);
    const int  k     = kk & 63;
    const float ck   = fmaf((float)k, Hstep, LOf);
    const int  phalf = t >> 7;

    unsigned long long a00 = 0, a01 = 0, a02 = 0, a03 = 0;
    unsigned long long a10 = 0, a11 = 0, a12 = 0, a13 = 0;

    const int n0 = chunk * CHUNK;

    for (int it = 0; it < ITERS; it++) {
        // ---- phase 0: per-pixel preprocessing (warp 0) ----
        if (t < PIX) {
            int n = n0 + it * PIX + t;
            float v0 = base[n] + EPSf;
            float v1 = base[N_PIX + n] + EPSf;
            float v2 = base[2 * N_PIX + n] + EPSf;
            float L[3];
            L[0] = __logf(v0);
            L[1] = __logf(v1);
            L[2] = __logf(v2);
            su[t]  = L[ch] - L[cu];
            sv[t]  = L[ch] - L[cv];
            siy[t] = sqrtf(fmaf(v0, v0, fmaf(v1, v1, v2 * v2))) * A2;
        }
        __syncthreads();

        // ---- phase 1: weight generation (inverse-quadratic RBF) ----
        #pragma unroll
        for (int j = 0; j < 16; j++) {
            int p = phalf + 2 * j;
            float d = isU ? su[p] : sv[p];
            float s = d - ck;
            float q = fmaf(s, s, A2);
            float r = frcp_nt(q);
            if (isU) {
                float w = siy[p] * r;                      // i_y * a^2 / q folded in
                *(float2*)&swu[p][k] = make_float2(w, w);  // duplicated pair
            } else {
                ((float*)&swv[p][0])[k] = A2 * r;
            }
        }
        __syncthreads();

        // ---- phase 2: outer-product accumulate (8 FFMA2 / pixel / thread) ----
        #pragma unroll
        for (int p = 0; p < PIX; p++) {
            ulonglong2 wu  = *(const ulonglong2*)&swu[p][2 * ug];
            ulonglong2 wva = *(const ulonglong2*)&swv[p][4 * vg];
            ulonglong2 wvb = *(const ulonglong2*)&swv[p][4 * vg + 2];
            FMA2(a00, wu.x, wva.x, a00);
            FMA2(a01, wu.x, wva.y, a01);
            FMA2(a02, wu.x, wvb.x, a02);
            FMA2(a03, wu.x, wvb.y, a03);
            FMA2(a10, wu.y, wva.x, a10);
            FMA2(a11, wu.y, wva.y, a11);
            FMA2(a12, wu.y, wvb.x, a12);
            FMA2(a13, wu.y, wvb.y, a13);
        }
        __syncthreads();
    }

    // store this block's 64x64 partial (deterministic, no atomics)
    unsigned long long* out = &g_partial[bx][0];
    int r0 = (2 * ug) * 32 + 4 * vg;   // row = u * 32 u64 per row
    int r1 = r0 + 32;
    *(ulonglong2*)&out[r0]     = make_ulonglong2(a00, a01);
    *(ulonglong2*)&out[r0 + 2] = make_ulonglong2(a02, a03);
    *(ulonglong2*)&out[r1]     = make_ulonglong2(a10, a11);
    *(ulonglong2*)&out[r1 + 2] = make_ulonglong2(a12, a13);
}

// =====================================================================
// K2: reduce chunk partials -> hist per combo, plus per-combo totals
// =====================================================================
__global__ void __launch_bounds__(256) reduce_kernel() {
    const int co = blockIdx.x;
    const int t  = threadIdx.x;
    const float* pf = (const float*)g_partial + (size_t)co * NCHUNK * 4096;

    float tsum = 0.0f;
    for (int i = t; i < 4096; i += 256) {
        float s = 0.0f;
        #pragma unroll 8
        for (int c = 0; c < NCHUNK; c++)
            s += pf[(size_t)c * 4096 + i];
        g_hist[co][i] = s;
        tsum += s;
    }

    __shared__ float red[256];
    red[t] = tsum;
    __syncthreads();
    for (int s2 = 128; s2 > 0; s2 >>= 1) {
        if (t < s2) red[t] += red[t + s2];
        __syncthreads();
    }
    if (t == 0) g_csum[co] = red[0];
}

// =====================================================================
// K3: per-batch Hellinger-style distance between normalized hists
// =====================================================================
__global__ void __launch_bounds__(256) loss_kernel() {
    const int b = blockIdx.x;
    const int t = threadIdx.x;

    float tx = g_csum[b * 3] + g_csum[b * 3 + 1] + g_csum[b * 3 + 2];
    float ty = g_csum[24 + b * 3] + g_csum[24 + b * 3 + 1] + g_csum[24 + b * 3 + 2];
    float itx = 1.0f / tx;
    float ity = 1.0f / ty;

    float hs = 0.0f;
    for (int idx = t; idx < 3 * 4096; idx += 256) {
        int ch = idx >> 12;
        int i  = idx & 4095;
        float xv = g_hist[b * 3 + ch][i] * itx;
        float yv = g_hist[24 + b * 3 + ch][i] * ity;
        float d  = sqrtf(yv) - sqrtf(xv);
        hs = fmaf(d, d, hs);
    }

    __shared__ float red[256];
    red[t] = hs;
    __syncthreads();
    for (int s2 = 128; s2 > 0; s2 >>= 1) {
        if (t < s2) red[t] += red[t + s2];
        __syncthreads();
    }
    if (t == 0) g_hb[b] = red[0];
}

// =====================================================================
// K4: final scalar — mean over batch of sqrt(0.5 * h_b)
// =====================================================================
__global__ void final_kernel(float* __restrict__ out) {
    if (threadIdx.x == 0) {
        float s = 0.0f;
        for (int b = 0; b < 8; b++)
            s += sqrtf(g_hb[b] * 0.5f);
        out[0] = s * 0.125f;
    }
}

// =====================================================================
extern "C" void kernel_launch(void* const* d_in, const int* in_sizes, int n_in,
                              void* d_out, int out_size) {
    const float* x = (const float*)d_in[0];
    const float* y = (const float*)d_in[1];

    hist_kernel<<<NCOMBO * NCHUNK, THREADS>>>(x, y);
    reduce_kernel<<<NCOMBO, 256>>>();
    loss_kernel<<<8, 256>>>();
    final_kernel<<<1, 32>>>((float*)d_out);
}

// round 9
// speedup vs baseline: 1.4053x; 1.4053x over previous
#include <cuda_runtime.h>
#include <cstdint>

// ---------------- problem constants ----------------
#define NPIX   65536            // 256*256
#define LOf    (-3.0f)
#define Hstep  (6.0f / 63.0f)   // linspace(-3,3,64) spacing
#define A2     (4.0e-4f)        // FALL_OFF^2
#define EPSf   (1e-6f)

// ---------------- tiling ---------------------------
#define NIB    16               // (img,batch) pairs: 2*8
#define NCH    64               // pixel chunks per (img,batch)
#define CHUNK  1024             // pixels per block
#define PIX    16               // pixels per stage
#define NSTAGE (CHUNK / PIX)    // 64

// ---------------- static scratch -------------------
__device__ float g_partial[NIB * NCH][3 * 4096];   // 50 MB partial hists
__device__ float g_hist[NIB][3 * 4096];
__device__ float g_hb[8];

// ---------------- helpers --------------------------
__device__ __forceinline__ float frcp(float q) {
    float r;
    asm("rcp.approx.f32 %0, %1;" : "=f"(r) : "f"(q));
    return r;
}
__device__ __forceinline__ unsigned long long dup2(float w) {
    unsigned long long r;
    asm("mov.b64 %0, {%1, %1};" : "=l"(r) : "f"(w));
    return r;
}
// packed fp32x2 FMA (Blackwell FFMA2, only via PTX)
#define FMA2(d, a, b) \
    asm("fma.rn.f32x2 %0, %1, %2, %0;" : "+l"(d) : "l"(a), "l"(b))

// ---------------- SMEM (40 KB, static) -------------
struct SmemT {
    float s1[CHUNK], s2[CHUNK], s3[CHUNK], siy[CHUNK];   // 16 KB
    unsigned long long W1dup[PIX * 64];                  // 8 KB  (iy*A2*rcp(q1), dup pairs)
    unsigned long long W2dup[PIX * 64];                  // 8 KB  (iy*A2*rcp(q2), dup pairs)
    float W2pair[PIX * 64];                              // 4 KB  (A2*rcp(q2))
    float W3pair[PIX * 64];                              // 4 KB  (A2*rcp(q3))
};

// =====================================================================
// K1: per-(img,batch,chunk) — all 3 channel 64x64 histograms at once
//   H_r = sum iy*A2*rcp(q1)[u] * A2*rcp(q2)[v]
//   H_g[63-u][v]    uses W1[u] (g's u-weights are W1 reversed)
//   H_b[63-u][63-v] uses W2dup[u], W3[v] (both reversed)
// =====================================================================
__global__ void __launch_bounds__(256) hist_kernel(const float* __restrict__ x,
                                                   const float* __restrict__ y) {
    __shared__ SmemT sm;
    const int t  = threadIdx.x;
    const int bx = blockIdx.x;
    const int ib    = bx >> 6;        // 0..15
    const int chunk = bx & 63;
    const float* base = (ib < 8 ? x : y) + (size_t)(ib & 7) * 3 * NPIX + chunk * CHUNK;

    // ---- prep: logs + chroma diffs + intensity for the whole chunk ----
    {
        const int p = 4 * t;
        float4 c0 = *(const float4*)(base + p);
        float4 c1 = *(const float4*)(base + NPIX + p);
        float4 c2 = *(const float4*)(base + 2 * NPIX + p);
        float a0[4] = {c0.x, c0.y, c0.z, c0.w};
        float a1[4] = {c1.x, c1.y, c1.z, c1.w};
        float a2v[4] = {c2.x, c2.y, c2.z, c2.w};
        #pragma unroll
        for (int j = 0; j < 4; j++) {
            float v0 = a0[j] + EPSf, v1 = a1[j] + EPSf, v2 = a2v[j] + EPSf;
            float l0 = __logf(v0), l1 = __logf(v1), l2 = __logf(v2);
            sm.s1[p + j]  = l0 - l1;          // d1 = lr - lg
            sm.s2[p + j]  = l0 - l2;          // d2 = lr - lb
            sm.s3[p + j]  = l1 - l2;          // d3 = lg - lb
            sm.siy[p + j] = sqrtf(fmaf(v0, v0, fmaf(v1, v1, v2 * v2))) * A2;
        }
    }
    __syncthreads();

    // ---- gen mapping: 192 active threads own (vector, bin) ----
    const int vec = t >> 6;                    // 0,1,2 active; 3 idle
    const int k   = t & 63;
    const float ck = fmaf((float)k, Hstep, LOf);
    const float* S = (vec == 0) ? sm.s1 : (vec == 1 ? sm.s2 : sm.s3);

    // ---- consume mapping: 2u x 8v tile per thread, all 3 channels ----
    const int ug = t >> 3;                     // 0..31
    const int vg = t & 7;                      // 0..7
    unsigned long long ar[2][4] = {};          // ch r
    unsigned long long ag[2][4] = {};          // ch g
    unsigned long long ab[2][4] = {};          // ch b

    for (int st = 0; st < NSTAGE; st++) {
        // ---- phase 1: weight generation (MUFU rcp) ----
        if (vec < 3) {
            const float* Sp = S + st * PIX;
            const float* Yp = sm.siy + st * PIX;
            #pragma unroll
            for (int p = 0; p < PIX; p++) {
                float d = Sp[p] - ck;
                float r = frcp(fmaf(d, d, A2));
                if (vec == 0) {
                    sm.W1dup[p * 64 + k] = dup2(Yp[p] * r);
                } else if (vec == 1) {
                    sm.W2dup[p * 64 + k]  = dup2(Yp[p] * r);
                    sm.W2pair[p * 64 + k] = A2 * r;
                } else {
                    sm.W3pair[p * 64 + k] = A2 * r;
                }
            }
        }
        __syncthreads();

        // ---- phase 2: 3-channel outer-product accumulate (24 FFMA2/px) ----
        #pragma unroll
        for (int p = 0; p < PIX; p++) {
            ulonglong2 u1  = *(const ulonglong2*)&sm.W1dup[p * 64 + 2 * ug];
            ulonglong2 u2  = *(const ulonglong2*)&sm.W2dup[p * 64 + 2 * ug];
            ulonglong2 v2a = *(const ulonglong2*)&sm.W2pair[p * 64 + 8 * vg];
            ulonglong2 v2b = *(const ulonglong2*)&sm.W2pair[p * 64 + 8 * vg + 4];
            ulonglong2 v3a = *(const ulonglong2*)&sm.W3pair[p * 64 + 8 * vg];
            ulonglong2 v3b = *(const ulonglong2*)&sm.W3pair[p * 64 + 8 * vg + 4];
            // r: u = W1 (iy), v = W2
            FMA2(ar[0][0], u1.x, v2a.x); FMA2(ar[0][1], u1.x, v2a.y);
            FMA2(ar[0][2], u1.x, v2b.x); FMA2(ar[0][3], u1.x, v2b.y);
            FMA2(ar[1][0], u1.y, v2a.x); FMA2(ar[1][1], u1.y, v2a.y);
            FMA2(ar[1][2], u1.y, v2b.x); FMA2(ar[1][3], u1.y, v2b.y);
            // g: u = W1 (rows reversed at store), v = W3
            FMA2(ag[0][0], u1.x, v3a.x); FMA2(ag[0][1], u1.x, v3a.y);
            FMA2(ag[0][2], u1.x, v3b.x); FMA2(ag[0][3], u1.x, v3b.y);
            FMA2(ag[1][0], u1.y, v3a.x); FMA2(ag[1][1], u1.y, v3a.y);
            FMA2(ag[1][2], u1.y, v3b.x); FMA2(ag[1][3], u1.y, v3b.y);
            // b: u = W2dup (iy, rows reversed), v = W3 (cols reversed at store)
            FMA2(ab[0][0], u2.x, v3a.x); FMA2(ab[0][1], u2.x, v3a.y);
            FMA2(ab[0][2], u2.x, v3b.x); FMA2(ab[0][3], u2.x, v3b.y);
            FMA2(ab[1][0], u2.y, v3a.x); FMA2(ab[1][1], u2.y, v3a.y);
            FMA2(ab[1][2], u2.y, v3b.x); FMA2(ab[1][3], u2.y, v3b.y);
        }
        __syncthreads();
    }

    // ---- epilogue: write 3x64x64 with index remapping ----
    float* out = g_partial[bx];
    #pragma unroll
    for (int iu = 0; iu < 2; iu++) {
        const int u  = 2 * ug + iu;
        const int ur = 63 - u;
        #pragma unroll
        for (int jp = 0; jp < 4; jp++) {
            const int v = 8 * vg + 2 * jp;
            *(unsigned long long*)&out[u * 64 + v] = ar[iu][jp];
            *(unsigned long long*)&out[4096 + ur * 64 + v] = ag[iu][jp];
            // b: (lo,hi) lanes are v-bins (63-v, 62-v) -> store swapped at 62-v
            unsigned long long sw = (ab[iu][jp] >> 32) | (ab[iu][jp] << 32);
            *(unsigned long long*)&out[8192 + ur * 64 + (62 - v)] = sw;
        }
    }
}

// =====================================================================
// K2: reduce 64 chunk partials per (img,batch)
// =====================================================================
__global__ void __launch_bounds__(256) reduce_kernel() {
    const int ib  = blockIdx.x >> 3;
    const int seg = blockIdx.x & 7;
    const int e0  = seg * 1536;
    for (int e = e0 + threadIdx.x; e < e0 + 1536; e += 256) {
        float s = 0.0f;
        #pragma unroll 8
        for (int c = 0; c < NCH; c++)
            s += g_partial[ib * NCH + c][e];
        g_hist[ib][e] = s;
    }
}

// =====================================================================
// K3: per-batch totals + Hellinger-style distance (deterministic)
// =====================================================================
__global__ void __launch_bounds__(256) loss_kernel() {
    const int b = blockIdx.x;
    const int t = threadIdx.x;
    __shared__ float rx[256], ry[256];

    float sx = 0.0f, sy = 0.0f;
    for (int e = t; e < 3 * 4096; e += 256) {
        sx += g_hist[b][e];
        sy += g_hist[8 + b][e];
    }
    rx[t] = sx; ry[t] = sy;
    __syncthreads();
    for (int s2 = 128; s2 > 0; s2 >>= 1) {
        if (t < s2) { rx[t] += rx[t + s2]; ry[t] += ry[t + s2]; }
        __syncthreads();
    }
    const float itx = 1.0f / rx[0];
    const float ity = 1.0f / ry[0];
    __syncthreads();

    float hs = 0.0f;
    for (int e = t; e < 3 * 4096; e += 256) {
        float d = sqrtf(g_hist[8 + b][e] * ity) - sqrtf(g_hist[b][e] * itx);
        hs = fmaf(d, d, hs);
    }
    rx[t] = hs;
    __syncthreads();
    for (int s2 = 128; s2 > 0; s2 >>= 1) {
        if (t < s2) rx[t] += rx[t + s2];
        __syncthreads();
    }
    if (t == 0) g_hb[b] = rx[0];
}

// =====================================================================
// K4: final scalar — mean over batch of sqrt(0.5 * h_b)
// =====================================================================
__global__ void final_kernel(float* __restrict__ out) {
    if (threadIdx.x == 0) {
        float s = 0.0f;
        for (int b = 0; b < 8; b++)
            s += sqrtf(g_hb[b] * 0.5f);
        out[0] = s * 0.125f;
    }
}

// =====================================================================
extern "C" void kernel_launch(void* const* d_in, const int* in_sizes, int n_in,
                              void* d_out, int out_size) {
    const float* x = (const float*)d_in[0];
    const float* y = (const float*)d_in[1];

    hist_kernel<<<NIB * NCH, 256>>>(x, y);
    reduce_kernel<<<NIB * 8, 256>>>();
    loss_kernel<<<8, 256>>>();
    final_kernel<<<1, 32>>>((float*)d_out);
}

// round 11
// speedup vs baseline: 1.4664x; 1.0435x over previous
#include <cuda_runtime.h>
#include <cstdint>

// ---------------- problem constants ----------------
#define NPIX   65536            // 256*256
#define LOf    (-3.0f)
#define Hstep  (6.0f / 63.0f)   // linspace(-3,3,64) spacing
#define A2     (4.0e-4f)        // FALL_OFF^2
#define EPSf   (1e-6f)

// ---------------- tiling ---------------------------
#define NIB    16               // (img,batch) pairs: 2*8
#define NCH    128              // pixel chunks per (img,batch)
#define CHUNK  512              // pixels per block
#define PIX    16               // pixels per stage
#define NSTAGE (CHUNK / PIX)    // 32
#define NBLK   (NIB * NCH)      // 2048

// ---------------- static scratch -------------------
__device__ float g_partial[NBLK][3 * 4096];   // ~100 MB partial hists
__device__ float g_hist[NIB][3 * 4096];
__device__ float g_hb[8];

// ---------------- helpers --------------------------
__device__ __forceinline__ float frcp(float q) {
    float r;
    asm("rcp.approx.f32 %0, %1;" : "=f"(r) : "f"(q));
    return r;
}
__device__ __forceinline__ unsigned long long dup2(float w) {
    unsigned long long r;
    asm("mov.b64 %0, {%1, %1};" : "=l"(r) : "f"(w));
    return r;
}
// packed fp32x2 FMA (Blackwell FFMA2, only via PTX)
#define FMA2(d, a, b) \
    asm("fma.rn.f32x2 %0, %1, %2, %0;" : "+l"(d) : "l"(a), "l"(b))

// ---------------- SMEM (56 KB, static) -------------
struct SmemT {
    float s1[CHUNK], s2[CHUNK], s3[CHUNK], siy[CHUNK];     // 8 KB
    unsigned long long W1dup[2][PIX * 64];                 // 16 KB (iy*A2*rcp(q1), dup pairs)
    unsigned long long W2dup[2][PIX * 64];                 // 16 KB (iy*A2*rcp(q2), dup pairs)
    float W2pair[2][PIX * 64];                             // 8 KB  (A2*rcp(q2))
    float W3pair[2][PIX * 64];                             // 8 KB  (A2*rcp(q3))
};

// =====================================================================
// K1: per-(img,batch,chunk) — all 3 channel 64x64 histograms at once.
// Software-pipelined: gen(stage st+1) overlaps consume(stage st).
//   H_r[u][v]       = sum iy*A2*rcp(q1)[u] * A2*rcp(q2)[v]
//   H_g[63-u][v]    reuses W1[u] (u-weights reversed)
//   H_b[63-u][63-v] reuses W2dup[u], W3[v] (both reversed)
// =====================================================================
__global__ void __launch_bounds__(256, 2) hist_kernel(const float* __restrict__ x,
                                                      const float* __restrict__ y) {
    __shared__ SmemT sm;
    const int t  = threadIdx.x;
    const int bx = blockIdx.x;
    const int ib    = bx >> 7;            // 0..15
    const int chunk = bx & (NCH - 1);
    const float* base = (ib < 8 ? x : y) + (size_t)(ib & 7) * 3 * NPIX + chunk * CHUNK;

    // ---- prep: logs + chroma diffs + intensity for the whole chunk ----
    {
        const int p = 2 * t;
        float2 c0 = *(const float2*)(base + p);
        float2 c1 = *(const float2*)(base + NPIX + p);
        float2 c2 = *(const float2*)(base + 2 * NPIX + p);
        float a0[2] = {c0.x, c0.y};
        float a1[2] = {c1.x, c1.y};
        float a2v[2] = {c2.x, c2.y};
        #pragma unroll
        for (int j = 0; j < 2; j++) {
            float v0 = a0[j] + EPSf, v1 = a1[j] + EPSf, v2 = a2v[j] + EPSf;
            float l0 = __logf(v0), l1 = __logf(v1), l2 = __logf(v2);
            sm.s1[p + j]  = l0 - l1;          // d1 = lr - lg
            sm.s2[p + j]  = l0 - l2;          // d2 = lr - lb
            sm.s3[p + j]  = l1 - l2;          // d3 = lg - lb
            sm.siy[p + j] = sqrtf(fmaf(v0, v0, fmaf(v1, v1, v2 * v2))) * A2;
        }
    }

    // ---- gen mapping: 192 active threads own (vector, bin) ----
    const int vec = t >> 6;                    // 0,1,2 active; 3 idle
    const int k   = t & 63;
    const float ck = fmaf((float)k, Hstep, LOf);
    const float* S = (vec == 0) ? sm.s1 : (vec == 1 ? sm.s2 : sm.s3);

    // ---- consume mapping: 2u x 8v tile per thread, all 3 channels ----
    const int ug = t >> 3;                     // 0..31
    const int vg = t & 7;                      // 0..7
    unsigned long long ar[2][4] = {};          // ch r
    unsigned long long ag[2][4] = {};          // ch g
    unsigned long long ab[2][4] = {};          // ch b

    __syncthreads();

    // prologue: generate stage 0 into buffer 0
    if (vec < 3) {
        const float* Yp = sm.siy;
        #pragma unroll
        for (int p = 0; p < PIX; p++) {
            float d = S[p] - ck;
            float r = frcp(fmaf(d, d, A2));
            if (vec == 0) {
                sm.W1dup[0][p * 64 + k] = dup2(Yp[p] * r);
            } else if (vec == 1) {
                sm.W2dup[0][p * 64 + k]  = dup2(Yp[p] * r);
                sm.W2pair[0][p * 64 + k] = A2 * r;
            } else {
                sm.W3pair[0][p * 64 + k] = A2 * r;
            }
        }
    }
    __syncthreads();

    for (int st = 0; st < NSTAGE; st++) {
        const int buf = st & 1;

        // ---- gen stage st+1 into the other buffer (overlaps with FMA below) ----
        if (st + 1 < NSTAGE && vec < 3) {
            const int nb = buf ^ 1;
            const float* Sp = S + (st + 1) * PIX;
            const float* Yp = sm.siy + (st + 1) * PIX;
            #pragma unroll
            for (int p = 0; p < PIX; p++) {
                float d = Sp[p] - ck;
                float r = frcp(fmaf(d, d, A2));
                if (vec == 0) {
                    sm.W1dup[nb][p * 64 + k] = dup2(Yp[p] * r);
                } else if (vec == 1) {
                    sm.W2dup[nb][p * 64 + k]  = dup2(Yp[p] * r);
                    sm.W2pair[nb][p * 64 + k] = A2 * r;
                } else {
                    sm.W3pair[nb][p * 64 + k] = A2 * r;
                }
            }
        }

        // ---- consume stage st: 3-channel outer product (24 FFMA2/px) ----
        #pragma unroll
        for (int p = 0; p < PIX; p++) {
            ulonglong2 u1  = *(const ulonglong2*)&sm.W1dup[buf][p * 64 + 2 * ug];
            ulonglong2 u2  = *(const ulonglong2*)&sm.W2dup[buf][p * 64 + 2 * ug];
            ulonglong2 v2a = *(const ulonglong2*)&sm.W2pair[buf][p * 64 + 8 * vg];
            ulonglong2 v2b = *(const ulonglong2*)&sm.W2pair[buf][p * 64 + 8 * vg + 4];
            ulonglong2 v3a = *(const ulonglong2*)&sm.W3pair[buf][p * 64 + 8 * vg];
            ulonglong2 v3b = *(const ulonglong2*)&sm.W3pair[buf][p * 64 + 8 * vg + 4];
            // r: u = W1 (iy), v = W2
            FMA2(ar[0][0], u1.x, v2a.x); FMA2(ar[0][1], u1.x, v2a.y);
            FMA2(ar[0][2], u1.x, v2b.x); FMA2(ar[0][3], u1.x, v2b.y);
            FMA2(ar[1][0], u1.y, v2a.x); FMA2(ar[1][1], u1.y, v2a.y);
            FMA2(ar[1][2], u1.y, v2b.x); FMA2(ar[1][3], u1.y, v2b.y);
            // g: u = W1 (rows reversed at store), v = W3
            FMA2(ag[0][0], u1.x, v3a.x); FMA2(ag[0][1], u1.x, v3a.y);
            FMA2(ag[0][2], u1.x, v3b.x); FMA2(ag[0][3], u1.x, v3b.y);
            FMA2(ag[1][0], u1.y, v3a.x); FMA2(ag[1][1], u1.y, v3a.y);
            FMA2(ag[1][2], u1.y, v3b.x); FMA2(ag[1][3], u1.y, v3b.y);
            // b: u = W2dup (iy, rows reversed), v = W3 (cols reversed at store)
            FMA2(ab[0][0], u2.x, v3a.x); FMA2(ab[0][1], u2.x, v3a.y);
            FMA2(ab[0][2], u2.x, v3b.x); FMA2(ab[0][3], u2.x, v3b.y);
            FMA2(ab[1][0], u2.y, v3a.x); FMA2(ab[1][1], u2.y, v3a.y);
            FMA2(ab[1][2], u2.y, v3b.x); FMA2(ab[1][3], u2.y, v3b.y);
        }
        __syncthreads();
    }

    // ---- epilogue: write 3x64x64 with index remapping ----
    float* out = g_partial[bx];
    #pragma unroll
    for (int iu = 0; iu < 2; iu++) {
        const int u  = 2 * ug + iu;
        const int ur = 63 - u;
        #pragma unroll
        for (int jp = 0; jp < 4; jp++) {
            const int v = 8 * vg + 2 * jp;
            *(unsigned long long*)&out[u * 64 + v] = ar[iu][jp];
            *(unsigned long long*)&out[4096 + ur * 64 + v] = ag[iu][jp];
            // b: (lo,hi) lanes are v-bins (63-v, 62-v) -> store swapped at 62-v
            unsigned long long sw = (ab[iu][jp] >> 32) | (ab[iu][jp] << 32);
            *(unsigned long long*)&out[8192 + ur * 64 + (62 - v)] = sw;
        }
    }
}

// =====================================================================
// K2: reduce 128 chunk partials per (img,batch)
// =====================================================================
__global__ void __launch_bounds__(256) reduce_kernel() {
    const int ib  = blockIdx.x >> 3;
    const int seg = blockIdx.x & 7;
    const int e0  = seg * 1536;
    for (int e = e0 + threadIdx.x; e < e0 + 1536; e += 256) {
        float s = 0.0f;
        #pragma unroll 8
        for (int c = 0; c < NCH; c++)
            s += g_partial[ib * NCH + c][e];
        g_hist[ib][e] = s;
    }
}

// =====================================================================
// K3: per-batch totals + Hellinger-style distance (deterministic)
// =====================================================================
__global__ void __launch_bounds__(256) loss_kernel() {
    const int b = blockIdx.x;
    const int t = threadIdx.x;
    __shared__ float rx[256], ry[256];

    float sx = 0.0f, sy = 0.0f;
    for (int e = t; e < 3 * 4096; e += 256) {
        sx += g_hist[b][e];
        sy += g_hist[8 + b][e];
    }
    rx[t] = sx; ry[t] = sy;
    __syncthreads();
    for (int s2 = 128; s2 > 0; s2 >>= 1) {
        if (t < s2) { rx[t] += rx[t + s2]; ry[t] += ry[t + s2]; }
        __syncthreads();
    }
    const float itx = 1.0f / rx[0];
    const float ity = 1.0f / ry[0];
    __syncthreads();

    float hs = 0.0f;
    for (int e = t; e < 3 * 4096; e += 256) {
        float d = sqrtf(g_hist[8 + b][e] * ity) - sqrtf(g_hist[b][e] * itx);
        hs = fmaf(d, d, hs);
    }
    rx[t] = hs;
    __syncthreads();
    for (int s2 = 128; s2 > 0; s2 >>= 1) {
        if (t < s2) rx[t] += rx[t + s2];
        __syncthreads();
    }
    if (t == 0) g_hb[b] = rx[0];
}

// =====================================================================
// K4: final scalar — mean over batch of sqrt(0.5 * h_b)
// =====================================================================
__global__ void final_kernel(float* __restrict__ out) {
    if (threadIdx.x == 0) {
        float s = 0.0f;
        for (int b = 0; b < 8; b++)
            s += sqrtf(g_hb[b] * 0.5f);
        out[0] = s * 0.125f;
    }
}

// =====================================================================
// K5: no-op launch-slot shifter so ncu's "-s 5 -c 1" captures hist_kernel
// (5 launches per kernel_launch call -> the 6th launch is hist of call 2)
// =====================================================================
__global__ void pad_kernel(float* __restrict__ out) {
    if (threadIdx.x > 1024) out[0] = 0.0f;   // never true; no work
}

// =====================================================================
extern "C" void kernel_launch(void* const* d_in, const int* in_sizes, int n_in,
                              void* d_out, int out_size) {
    const float* x = (const float*)d_in[0];
    const float* y = (const float*)d_in[1];

    hist_kernel<<<NBLK, 256>>>(x, y);
    reduce_kernel<<<NIB * 8, 256>>>();
    loss_kernel<<<8, 256>>>();
    final_kernel<<<1, 32>>>((float*)d_out);
    pad_kernel<<<1, 32>>>((float*)d_out);
}

// round 13
// speedup vs baseline: 8.8853x; 6.0592x over previous
#include <cuda_runtime.h>
#include <cstdint>

// ---------------- problem constants ----------------
#define NPIX   65536            // 256*256
#define LOf    (-3.0f)
#define Hstep  (6.0f / 63.0f)   // linspace(-3,3,64) spacing
#define A2     (4.0e-4f)        // FALL_OFF^2
#define EPSf   (1e-6f)
#define SCALE  64.0f            // fp16 range management; cancels in normalization

// ---------------- tiling ---------------------------
#define NIB    16               // (img,batch): 2*8
#define NCH    128              // chunks per (img,batch)
#define KPIX   512              // pixels per block
#define SPX    64               // pixels per stage (mma K-window)
#define NSTG   (KPIX / SPX)     // 8
#define NBLK   (NIB * NCH)      // 2048

// SMEM layout (dynamic, 57344 B):
//   [0, 8192):  s1,s2,s3,siy  (4 x 512 f32)
//   [8192 + buf*24576 + j*8192): W_j stage matrix, 64 bins x 64 px fp16,
//       128 B rows, SW128 xor-swizzle ((row&7)<<4)
#define SMEM_SZ   57344
#define W_OFF     8192
#define W_BUFSTR  24576

// ---------------- static scratch -------------------
__device__ float g_partial[NBLK][3 * 4096];   // ~100 MB
__device__ float g_hist[NIB][3 * 4096];
__device__ float g_hb[8];

// ---------------- helpers --------------------------
__device__ __forceinline__ uint32_t smem_u32(const void* p) {
    uint32_t a;
    asm("{ .reg .u64 t; cvta.to.shared.u64 t, %1; cvt.u32.u64 %0, t; }" : "=r"(a) : "l"(p));
    return a;
}
__device__ __forceinline__ float frcp(float q) {
    float r;
    asm("rcp.approx.f32 %0, %1;" : "=f"(r) : "f"(q));
    return r;
}
#define STS32(addr, val) \
    asm volatile("st.shared.b32 [%0], %1;" :: "r"(addr), "r"(val) : "memory")

#define LDSM4(r0, r1, r2, r3, addr) \
    asm volatile("ldmatrix.sync.aligned.m8n8.x4.shared.b16 {%0,%1,%2,%3}, [%4];" \
        : "=r"(r0), "=r"(r1), "=r"(r2), "=r"(r3) : "r"(addr))

#define MMA4(d, a, b0, b1) \
    asm volatile("mma.sync.aligned.m16n8k16.row.col.f32.f16.f16.f32 " \
        "{%0,%1,%2,%3}, {%4,%5,%6,%7}, {%8,%9}, {%0,%1,%2,%3};" \
        : "+f"((d)[0]), "+f"((d)[1]), "+f"((d)[2]), "+f"((d)[3]) \
        : "r"((a)[0]), "r"((a)[1]), "r"((a)[2]), "r"((a)[3]), "r"(b0), "r"(b1))

// =====================================================================
// weight generation for one 64-px stage into buffer wb
// thread role: g = t>>6 (0..3), k = t&63.
//   g 0..2: matrix j=g, bin k, px-pairs 0..23 (px 0..47)
//   g 3   : all 3 matrices, bin k, px-pairs 24..31 (px 48..63)
// px-pair rotation by k>>3 kills the 4-way STS bank conflict.
// =====================================================================
__device__ __forceinline__ void gen_stage(
    int st, uint32_t wb, const float* s1, const float* s2, const float* s3,
    const float* siy, int g, int k, float ck)
{
    const int sb = st * SPX;
    const uint32_t kxor = (uint32_t)(k & 7) << 4;
    if (g < 3) {
        const float* S = (g == 0) ? s1 : (g == 1 ? s2 : s3);
        const uint32_t rowa = wb + (uint32_t)g * 8192u + (uint32_t)k * 128u;
        const int rot = 6 * ((k >> 3) & 3);
        #pragma unroll
        for (int pp = 0; pp < 24; pp++) {
            int ppr = pp + rot; if (ppr >= 24) ppr -= 24;
            const int px = sb + 2 * ppr;
            float2 sv = *(const float2*)(S + px);
            float2 yv = *(const float2*)(siy + px);
            float d0 = sv.x - ck, d1 = sv.y - ck;
            float w0 = yv.x * frcp(fmaf(d0, d0, A2));
            float w1 = yv.y * frcp(fmaf(d1, d1, A2));
            uint32_t pk;
            asm("cvt.rn.f16x2.f32 %0, %1, %2;" : "=r"(pk) : "f"(w1), "f"(w0));
            STS32(rowa + (((uint32_t)(4 * ppr)) ^ kxor), pk);
        }
    } else {
        const int rot = 2 * ((k >> 3) & 3);
        #pragma unroll
        for (int j = 0; j < 3; j++) {
            const float* S = (j == 0) ? s1 : (j == 1 ? s2 : s3);
            const uint32_t rowa = wb + (uint32_t)j * 8192u + (uint32_t)k * 128u;
            #pragma unroll
            for (int pq = 0; pq < 8; pq++) {
                const int ppr = 24 + ((pq + rot) & 7);
                const int px = sb + 2 * ppr;
                float2 sv = *(const float2*)(S + px);
                float2 yv = *(const float2*)(siy + px);
                float d0 = sv.x - ck, d1 = sv.y - ck;
                float w0 = yv.x * frcp(fmaf(d0, d0, A2));
                float w1 = yv.y * frcp(fmaf(d1, d1, A2));
                uint32_t pk;
                asm("cvt.rn.f16x2.f32 %0, %1, %2;" : "=r"(pk) : "f"(w1), "f"(w0));
                STS32(rowa + (((uint32_t)(4 * ppr)) ^ kxor), pk);
            }
        }
    }
}

// =====================================================================
// K1: tensor-core histogram. Per block: (img,batch) x 512-px chunk.
//   a_j[k][px] = SCALE*sqrt(iy)*A2*rcp((d_j-c_k)^2+A2)  (fp16)
//   H_r = a1*a2^T; H_g[u,v] = (a1*a3^T)[63-u, v]; H_b[u,v] = (a2*a3^T)[63-u,63-v]
// =====================================================================
__global__ void __launch_bounds__(256, 2) hist_kernel(const float* __restrict__ x,
                                                      const float* __restrict__ y) {
    extern __shared__ __align__(16) unsigned char smem_raw[];
    float* s1  = (float*)smem_raw;
    float* s2  = s1 + KPIX;
    float* s3  = s2 + KPIX;
    float* siy = s3 + KPIX;
    const uint32_t smb = smem_u32(smem_raw);

    const int t  = threadIdx.x;
    const int bx = blockIdx.x;
    const int ib    = bx >> 7;               // 0..15
    const int chunk = bx & (NCH - 1);
    const float* base = (ib < 8 ? x : y) + (size_t)(ib & 7) * 3 * NPIX + chunk * KPIX;

    // ---- prep: chroma diffs + scaled sqrt-intensity ----
    {
        const int p = 2 * t;
        float2 c0 = *(const float2*)(base + p);
        float2 c1 = *(const float2*)(base + NPIX + p);
        float2 c2 = *(const float2*)(base + 2 * NPIX + p);
        float a0[2] = {c0.x, c0.y}, a1[2] = {c1.x, c1.y}, a2v[2] = {c2.x, c2.y};
        #pragma unroll
        for (int j = 0; j < 2; j++) {
            float v0 = a0[j] + EPSf, v1 = a1[j] + EPSf, v2 = a2v[j] + EPSf;
            float l0 = __logf(v0), l1 = __logf(v1), l2 = __logf(v2);
            s1[p + j] = l0 - l1;             // d1 = lr - lg
            s2[p + j] = l0 - l2;             // d2 = lr - lb
            s3[p + j] = l1 - l2;             // d3 = lg - lb
            float ss = fmaf(v0, v0, fmaf(v1, v1, v2 * v2));
            siy[p + j] = (SCALE * A2) * sqrtf(sqrtf(ss));   // SCALE*sqrt(iy)*A2
        }
    }

    // gen role
    const int g = t >> 6, k = t & 63;
    const float ck = fmaf((float)k, Hstep, LOf);

    // mma role: warp w -> rows [mr,mr+16), cols [nc,nc+32)
    const int w = t >> 5, lane = t & 31;
    const int mr = 16 * (w >> 1), nc = 32 * (w & 1);
    const int rr = lane & 7;
    const uint32_t arow = (uint32_t)(mr + rr + 8 * ((lane >> 3) & 1)) * 128u;
    const uint32_t akh  = (uint32_t)(lane >> 4) * 16u;
    const uint32_t brow = (uint32_t)(nc + rr + 8 * (lane >> 4)) * 128u;
    const uint32_t bkh  = (uint32_t)((lane >> 3) & 1) * 16u;
    const uint32_t sxor = (uint32_t)rr << 4;

    float ar[16] = {}, ag[16] = {}, ab[16] = {};

    __syncthreads();
    gen_stage(0, smb + W_OFF, s1, s2, s3, siy, g, k, ck);
    __syncthreads();

    for (int st = 0; st < NSTG; st++) {
        const uint32_t wb = smb + W_OFF + (uint32_t)(st & 1) * W_BUFSTR;
        if (st + 1 < NSTG)
            gen_stage(st + 1, smb + W_OFF + (uint32_t)((st & 1) ^ 1) * W_BUFSTR,
                      s1, s2, s3, siy, g, k, ck);

        const uint32_t w1b = wb, w2b = wb + 8192u, w3b = wb + 16384u;
        #pragma unroll
        for (int ks = 0; ks < 4; ks++) {
            const uint32_t offA = (32u * ks + akh) ^ sxor;
            const uint32_t offB = (32u * ks + bkh) ^ sxor;
            uint32_t A1[4], A2r[4], B2[8], B3[8];
            LDSM4(A1[0], A1[1], A1[2], A1[3],   w1b + arow + offA);
            LDSM4(A2r[0], A2r[1], A2r[2], A2r[3], w2b + arow + offA);
            LDSM4(B2[0], B2[1], B2[2], B2[3],   w2b + brow + offB);
            LDSM4(B2[4], B2[5], B2[6], B2[7],   w2b + brow + 2048u + offB);
            LDSM4(B3[0], B3[1], B3[2], B3[3],   w3b + brow + offB);
            LDSM4(B3[4], B3[5], B3[6], B3[7],   w3b + brow + 2048u + offB);
            #pragma unroll
            for (int j = 0; j < 4; j++) {
                MMA4(ar + 4 * j, A1,  B2[2 * j], B2[2 * j + 1]);
                MMA4(ag + 4 * j, A1,  B3[2 * j], B3[2 * j + 1]);
                MMA4(ab + 4 * j, A2r, B3[2 * j], B3[2 * j + 1]);
            }
        }
        __syncthreads();
    }

    // ---- epilogue: store with channel bin-reversal folded in ----
    float* op = g_partial[bx];
    const int r = lane >> 2, c = 2 * (lane & 3);
    #pragma unroll
    for (int j = 0; j < 4; j++) {
        const int col = nc + 8 * j + c;
        const int u0 = mr + r, u1 = u0 + 8;
        *(float2*)&op[u0 * 64 + col] = make_float2(ar[4 * j],     ar[4 * j + 1]);
        *(float2*)&op[u1 * 64 + col] = make_float2(ar[4 * j + 2], ar[4 * j + 3]);
        *(float2*)&op[4096 + (63 - u0) * 64 + col] = make_float2(ag[4 * j],     ag[4 * j + 1]);
        *(float2*)&op[4096 + (63 - u1) * 64 + col] = make_float2(ag[4 * j + 2], ag[4 * j + 3]);
        *(float2*)&op[8192 + (63 - u0) * 64 + (62 - col)] = make_float2(ab[4 * j + 1], ab[4 * j]);
        *(float2*)&op[8192 + (63 - u1) * 64 + (62 - col)] = make_float2(ab[4 * j + 3], ab[4 * j + 2]);
    }
}

// =====================================================================
// K2: reduce 128 chunk partials per (img,batch)
// =====================================================================
__global__ void __launch_bounds__(256) reduce_kernel() {
    const int ib  = blockIdx.x / 24;
    const int seg = blockIdx.x % 24;
    const int e0  = seg * 512;
    for (int e = e0 + threadIdx.x; e < e0 + 512; e += 256) {
        float s = 0.0f;
        #pragma unroll 8
        for (int c = 0; c < NCH; c++)
            s += g_partial[ib * NCH + c][e];
        g_hist[ib][e] = s;
    }
}

// =====================================================================
// K3: per-batch totals + Hellinger-style distance
// =====================================================================
__global__ void __launch_bounds__(256) loss_kernel() {
    const int b = blockIdx.x;
    const int t = threadIdx.x;
    __shared__ float rx[256], ry[256];

    float sx = 0.0f, sy = 0.0f;
    for (int e = t; e < 3 * 4096; e += 256) {
        sx += g_hist[b][e];
        sy += g_hist[8 + b][e];
    }
    rx[t] = sx; ry[t] = sy;
    __syncthreads();
    for (int s2 = 128; s2 > 0; s2 >>= 1) {
        if (t < s2) { rx[t] += rx[t + s2]; ry[t] += ry[t + s2]; }
        __syncthreads();
    }
    const float itx = 1.0f / rx[0];
    const float ity = 1.0f / ry[0];
    __syncthreads();

    float hs = 0.0f;
    for (int e = t; e < 3 * 4096; e += 256) {
        float d = sqrtf(g_hist[8 + b][e] * ity) - sqrtf(g_hist[b][e] * itx);
        hs = fmaf(d, d, hs);
    }
    rx[t] = hs;
    __syncthreads();
    for (int s2 = 128; s2 > 0; s2 >>= 1) {
        if (t < s2) rx[t] += rx[t + s2];
        __syncthreads();
    }
    if (t == 0) g_hb[b] = rx[0];
}

// =====================================================================
// K4: final scalar — mean over batch of sqrt(0.5 * h_b)
// =====================================================================
__global__ void final_kernel(float* __restrict__ out) {
    if (threadIdx.x == 0) {
        float s = 0.0f;
        for (int b = 0; b < 8; b++)
            s += sqrtf(g_hb[b] * 0.5f);
        out[0] = s * 0.125f;
    }
}

// =====================================================================
extern "C" void kernel_launch(void* const* d_in, const int* in_sizes, int n_in,
                              void* d_out, int out_size) {
    const float* x = (const float*)d_in[0];
    const float* y = (const float*)d_in[1];

    cudaFuncSetAttribute(hist_kernel, cudaFuncAttributeMaxDynamicSharedMemorySize, SMEM_SZ);
    hist_kernel<<<NBLK, 256, SMEM_SZ>>>(x, y);
    reduce_kernel<<<NIB * 24, 256>>>();
    loss_kernel<<<8, 256>>>();
    final_kernel<<<1, 32>>>((float*)d_out);
}